// round 10
// baseline (speedup 1.0000x reference)
#include <cuda_runtime.h>
#include <math_constants.h>

#define B_    64
#define C_    256
#define HW_   4096          // floats per plane = 1024 float4
#define NPLANE (B_*C_)      // 16384
#define NCL   8
#define BLKS_PER_SAMPLE 32  // 2048 blocks / 64 samples

__device__ float g_sum[NPLANE];
__device__ float g_min[NPLANE];
__device__ float g_max[NPLANE];
__device__ float g_scale[NPLANE];
__device__ float g_smin[B_];
__device__ float g_smax[B_];
__device__ float g_ss[B_];
__device__ float g_zz[B_];
__device__ float g_inv[B_];
__device__ unsigned g_scnt[B_];   // per-sample arrival counters (self-resetting)
__device__ unsigned g_dcnt;       // sample-finisher counter (self-resetting)

// ============ kernel 1: stats + (dependency-driven) SE MLP + ranges =========
// 2048 blocks x 256 threads. Block bl covers planes 8bl..8bl+7 (one warp each),
// all inside sample bl/32. 32nd finishing block of a sample runs that sample's
// SE MLP inline; 64th finishing sample runs the cluster-range stage inline.
__global__ __launch_bounds__(256) void k123(const float* __restrict__ x,
                                            const float* __restrict__ w1,
                                            const float* __restrict__ b1,
                                            const float* __restrict__ w2,
                                            const float* __restrict__ b2,
                                            const float* __restrict__ act_range,
                                            const int*   __restrict__ cluster) {
    const int t     = threadIdx.x;
    const int warp  = t >> 5;
    const int lane  = t & 31;
    const int plane = blockIdx.x * 8 + warp;
    const int sample = blockIdx.x / BLKS_PER_SAMPLE;

    // ---- phase A: per-plane sum / min / max (warp-per-plane) ----
    {
        const float4* xp = reinterpret_cast<const float4*>(x + (size_t)plane * HW_);
        float s0 = 0.f, s1 = 0.f;
        float mn0 = CUDART_INF_F, mn1 = CUDART_INF_F;
        float mx0 = -CUDART_INF_F, mx1 = -CUDART_INF_F;
#pragma unroll 4
        for (int i = 0; i < 32; i += 2) {
            float4 a = xp[lane + 32 * i];
            float4 b = xp[lane + 32 * (i + 1)];
            s0 += (a.x + a.y) + (a.z + a.w);
            mn0 = fminf(mn0, fminf(fminf(a.x, a.y), fminf(a.z, a.w)));
            mx0 = fmaxf(mx0, fmaxf(fmaxf(a.x, a.y), fmaxf(a.z, a.w)));
            s1 += (b.x + b.y) + (b.z + b.w);
            mn1 = fminf(mn1, fminf(fminf(b.x, b.y), fminf(b.z, b.w)));
            mx1 = fmaxf(mx1, fmaxf(fmaxf(b.x, b.y), fmaxf(b.z, b.w)));
        }
        float s  = s0 + s1;
        float mn = fminf(mn0, mn1);
        float mx = fmaxf(mx0, mx1);
#pragma unroll
        for (int o = 16; o; o >>= 1) {
            s  += __shfl_xor_sync(0xffffffffu, s, o);
            mn  = fminf(mn, __shfl_xor_sync(0xffffffffu, mn, o));
            mx  = fmaxf(mx, __shfl_xor_sync(0xffffffffu, mx, o));
        }
        if (lane == 0) {
            g_sum[plane] = s;
            g_min[plane] = mn;
            g_max[plane] = mx;
        }
    }
    __syncthreads();

    // ---- arrival: am I the last block of my sample? ----
    __shared__ int sh_fin;
    if (t == 0) {
        __threadfence();                               // release my stats
        unsigned old = atomicAdd(&g_scnt[sample], 1u);
        sh_fin = (old == BLKS_PER_SAMPLE - 1u);
        if (sh_fin) g_scnt[sample] = 0u;               // last arriver resets
    }
    __syncthreads();
    if (!sh_fin) return;
    __threadfence();                                   // acquire peers' stats

    // ---- phase B: SE MLP for this sample (R8-coalesced) ----
    __shared__ float pooled[C_];
    __shared__ float hbuf[64];

    pooled[t] = g_sum[sample * C_ + t] * (1.0f / 4096.0f);
    __syncthreads();

#pragma unroll
    for (int k = 0; k < 8; ++k) {                      // 8 warps x 8 outputs
        const int o = warp * 8 + k;
        const float* row = w1 + o * C_;
        float acc = 0.f;
#pragma unroll
        for (int j = 0; j < 8; ++j)
            acc = fmaf(row[lane + 32 * j], pooled[lane + 32 * j], acc);
#pragma unroll
        for (int sh = 16; sh; sh >>= 1)
            acc += __shfl_xor_sync(0xffffffffu, acc, sh);
        if (lane == 0) hbuf[o] = fmaxf(acc + b1[o], 0.0f);
    }
    __syncthreads();

    float v = b2[t];
    const float4* w2r = reinterpret_cast<const float4*>(w2 + t * 64);
#pragma unroll
    for (int j = 0; j < 16; ++j) {
        float4 wv = w2r[j];
        v = fmaf(hbuf[4 * j + 0], wv.x, v);
        v = fmaf(hbuf[4 * j + 1], wv.y, v);
        v = fmaf(hbuf[4 * j + 2], wv.z, v);
        v = fmaf(hbuf[4 * j + 3], wv.w, v);
    }
    float sc = fminf(fmaxf(v * (1.0f / 6.0f) + 0.5f, 0.0f), 1.0f);
    g_scale[sample * C_ + t] = sc;

    float pmn = sc * g_min[sample * C_ + t];           // scale >= 0
    float pmx = sc * g_max[sample * C_ + t];
#pragma unroll
    for (int o = 16; o; o >>= 1) {
        pmn = fminf(pmn, __shfl_xor_sync(0xffffffffu, pmn, o));
        pmx = fmaxf(pmx, __shfl_xor_sync(0xffffffffu, pmx, o));
    }
    __shared__ float sh_mn[8], sh_mx[8];
    if (lane == 0) { sh_mn[warp] = pmn; sh_mx[warp] = pmx; }
    __syncthreads();
    if (t == 0) {
        float tmn = CUDART_INF_F, tmx = -CUDART_INF_F;
#pragma unroll
        for (int w = 0; w < 8; ++w) {
            tmn = fminf(tmn, sh_mn[w]);
            tmx = fmaxf(tmx, sh_mx[w]);
        }
        g_smin[sample] = tmn;
        g_smax[sample] = tmx;
    }
    __syncthreads();

    // ---- am I the last sample-finisher? ----
    __shared__ int sh_last;
    if (t == 0) {
        __threadfence();                               // release smin/smax
        unsigned o2 = atomicAdd(&g_dcnt, 1u);
        sh_last = (o2 == B_ - 1u);
        if (sh_last) g_dcnt = 0u;                      // reset for replay
    }
    __syncthreads();
    if (!sh_last) return;
    __threadfence();                                   // acquire all smin/smax

    // ---- phase C: cluster EMA ranges + per-sample (s,z) ----
    __shared__ float cs_s[NCL], cs_z[NCL];
    if (t < NCL) {
        float cmin = CUDART_INF_F, cmax = -CUDART_INF_F;
        for (int b = 0; b < B_; ++b) {
            if (cluster[b] == t) {
                cmin = fminf(cmin, g_smin[b]);
                cmax = fmaxf(cmax, g_smax[b]);
            }
        }
        const float SMOOTH = 0.995f, ONE_M = 0.005f;
        float nmin = act_range[2 * t]     * SMOOTH + cmin * ONE_M;
        float nmax = act_range[2 * t + 1] * SMOOTH + cmax * ONE_M;
        float s = (nmax - nmin) * (1.0f / 255.0f);
        cs_s[t] = s;
        cs_z[t] = -rintf(nmin / s);
    }
    __syncthreads();
    if (t < B_) {
        int k = cluster[t];
        g_ss[t]  = cs_s[k];
        g_zz[t]  = cs_z[k];
        g_inv[t] = 1.0f / cs_s[k];
    }
}

// ============ kernel 2: streaming scale + fake-quant (known-good) ===========
__global__ __launch_bounds__(256) void k4_quant(const float* __restrict__ x,
                                                float* __restrict__ out) {
    const int plane = blockIdx.x;
    const int b = plane >> 8;
    const float sc  = g_scale[plane];
    const float ssv = g_ss[b];
    const float zzv = g_zz[b];
    const float inv = g_inv[b];

    const float4* xp = reinterpret_cast<const float4*>(x   + (size_t)plane * HW_);
    float4*       op = reinterpret_cast<float4*>      (out + (size_t)plane * HW_);

#pragma unroll
    for (int i = 0; i < 4; ++i) {
        float4 v = xp[threadIdx.x + 256 * i];
        float4 r;
        {
            float o = sc * v.x;
            float q = fminf(fmaxf(rintf(fmaf(o, inv, zzv)), 0.0f), 255.0f);
            r.x = (q - zzv) * ssv;
        }
        {
            float o = sc * v.y;
            float q = fminf(fmaxf(rintf(fmaf(o, inv, zzv)), 0.0f), 255.0f);
            r.y = (q - zzv) * ssv;
        }
        {
            float o = sc * v.z;
            float q = fminf(fmaxf(rintf(fmaf(o, inv, zzv)), 0.0f), 255.0f);
            r.z = (q - zzv) * ssv;
        }
        {
            float o = sc * v.w;
            float q = fminf(fmaxf(rintf(fmaf(o, inv, zzv)), 0.0f), 255.0f);
            r.w = (q - zzv) * ssv;
        }
        op[threadIdx.x + 256 * i] = r;
    }
}

// ---------------- launch ----------------------------------------------------
extern "C" void kernel_launch(void* const* d_in, const int* in_sizes, int n_in,
                              void* d_out, int out_size) {
    const float* x          = (const float*)d_in[0];
    const float* w1         = (const float*)d_in[1];
    const float* b1         = (const float*)d_in[2];
    const float* w2         = (const float*)d_in[3];
    const float* b2         = (const float*)d_in[4];
    const float* act_range  = (const float*)d_in[5];
    const int*   cluster    = (const int*)d_in[6];
    float* out = (float*)d_out;

    k123<<<NPLANE / 8, 256>>>(x, w1, b1, w2, b2, act_range, cluster);
    k4_quant<<<NPLANE, 256>>>(x, out);
}

// round 11
// speedup vs baseline: 1.1320x; 1.1320x over previous
#include <cuda_runtime.h>
#include <math_constants.h>

#define B_    64
#define C_    256
#define HW_   4096          // floats per plane = 1024 float4
#define NPLANE (B_*C_)      // 16384
#define NCL   8

__device__ float g_sum[NPLANE];
__device__ float g_min[NPLANE];
__device__ float g_max[NPLANE];
__device__ float g_scale[NPLANE];
__device__ float g_smin[B_];
__device__ float g_smax[B_];
__device__ float g_ss[B_];
__device__ float g_zz[B_];
__device__ float g_inv[B_];
__device__ unsigned g_k2cnt;   // self-resetting counter for k2's finisher

// ---------------- kernel 1: per-plane sum/min/max, warp-per-plane (R9) ------
__global__ __launch_bounds__(256) void k1_reduce(const float* __restrict__ x) {
    const int warp  = threadIdx.x >> 5;
    const int lane  = threadIdx.x & 31;
    const int plane = blockIdx.x * 8 + warp;

    const float4* xp = reinterpret_cast<const float4*>(x + (size_t)plane * HW_);

    float s0 = 0.f, s1 = 0.f;
    float mn0 = CUDART_INF_F, mn1 = CUDART_INF_F;
    float mx0 = -CUDART_INF_F, mx1 = -CUDART_INF_F;
#pragma unroll 4
    for (int i = 0; i < 32; i += 2) {
        float4 a = xp[lane + 32 * i];
        float4 b = xp[lane + 32 * (i + 1)];
        s0 += (a.x + a.y) + (a.z + a.w);
        mn0 = fminf(mn0, fminf(fminf(a.x, a.y), fminf(a.z, a.w)));
        mx0 = fmaxf(mx0, fmaxf(fmaxf(a.x, a.y), fmaxf(a.z, a.w)));
        s1 += (b.x + b.y) + (b.z + b.w);
        mn1 = fminf(mn1, fminf(fminf(b.x, b.y), fminf(b.z, b.w)));
        mx1 = fmaxf(mx1, fmaxf(fmaxf(b.x, b.y), fmaxf(b.z, b.w)));
    }
    float s  = s0 + s1;
    float mn = fminf(mn0, mn1);
    float mx = fmaxf(mx0, mx1);
#pragma unroll
    for (int o = 16; o; o >>= 1) {
        s  += __shfl_xor_sync(0xffffffffu, s, o);
        mn  = fminf(mn, __shfl_xor_sync(0xffffffffu, mn, o));
        mx  = fmaxf(mx, __shfl_xor_sync(0xffffffffu, mx, o));
    }
    if (lane == 0) {
        g_sum[plane] = s;
        g_min[plane] = mn;
        g_max[plane] = mx;
    }
}

// ---------------- kernel 2: SE MLP + per-sample min/max + inline k3 ---------
// 64 blocks; last-finishing block computes cluster ranges + per-sample (s,z).
__global__ __launch_bounds__(256) void k2_se(const float* __restrict__ w1,
                                             const float* __restrict__ b1,
                                             const float* __restrict__ w2,
                                             const float* __restrict__ b2,
                                             const float* __restrict__ act_range,
                                             const int*   __restrict__ cluster) {
    const int b = blockIdx.x;
    const int t = threadIdx.x;
    const int lane = t & 31, warp = t >> 5;
    __shared__ float pooled[C_];
    __shared__ float hbuf[64];

    pooled[t] = g_sum[b * C_ + t] * (1.0f / 4096.0f);
    __syncthreads();

#pragma unroll
    for (int k = 0; k < 8; ++k) {                 // 8 warps x 8 outputs, coalesced
        const int o = warp * 8 + k;
        const float* row = w1 + o * C_;
        float acc = 0.f;
#pragma unroll
        for (int j = 0; j < 8; ++j)
            acc = fmaf(row[lane + 32 * j], pooled[lane + 32 * j], acc);
#pragma unroll
        for (int sh = 16; sh; sh >>= 1)
            acc += __shfl_xor_sync(0xffffffffu, acc, sh);
        if (lane == 0) hbuf[o] = fmaxf(acc + b1[o], 0.0f);
    }
    __syncthreads();

    float v = b2[t];
    const float4* w2r = reinterpret_cast<const float4*>(w2 + t * 64);
#pragma unroll
    for (int j = 0; j < 16; ++j) {
        float4 wv = w2r[j];
        v = fmaf(hbuf[4 * j + 0], wv.x, v);
        v = fmaf(hbuf[4 * j + 1], wv.y, v);
        v = fmaf(hbuf[4 * j + 2], wv.z, v);
        v = fmaf(hbuf[4 * j + 3], wv.w, v);
    }
    float sc = fminf(fmaxf(v * (1.0f / 6.0f) + 0.5f, 0.0f), 1.0f);
    g_scale[b * C_ + t] = sc;

    float pmn = sc * g_min[b * C_ + t];           // scale >= 0
    float pmx = sc * g_max[b * C_ + t];
#pragma unroll
    for (int o = 16; o; o >>= 1) {
        pmn = fminf(pmn, __shfl_xor_sync(0xffffffffu, pmn, o));
        pmx = fmaxf(pmx, __shfl_xor_sync(0xffffffffu, pmx, o));
    }
    __shared__ float sh_mn[8], sh_mx[8];
    if (lane == 0) { sh_mn[warp] = pmn; sh_mx[warp] = pmx; }
    __syncthreads();
    if (t == 0) {
        float tmn = CUDART_INF_F, tmx = -CUDART_INF_F;
#pragma unroll
        for (int w = 0; w < 8; ++w) {
            tmn = fminf(tmn, sh_mn[w]);
            tmx = fmaxf(tmx, sh_mx[w]);
        }
        g_smin[b] = tmn;
        g_smax[b] = tmx;
    }
    __syncthreads();

    // ---- last-finishing block runs the (tiny) cluster-range stage ----
    __shared__ int sh_last;
    if (t == 0) {
        __threadfence();                           // release smin/smax/scale
        unsigned old = atomicAdd(&g_k2cnt, 1u);
        sh_last = (old == B_ - 1u);
        if (sh_last) g_k2cnt = 0u;                 // reset for graph replay
    }
    __syncthreads();
    if (!sh_last) return;
    __threadfence();                               // acquire peers' smin/smax

    __shared__ float cs_s[NCL], cs_z[NCL];
    if (t < NCL) {
        float cmin = CUDART_INF_F, cmax = -CUDART_INF_F;
        for (int bb = 0; bb < B_; ++bb) {
            if (cluster[bb] == t) {
                cmin = fminf(cmin, g_smin[bb]);
                cmax = fmaxf(cmax, g_smax[bb]);
            }
        }
        const float SMOOTH = 0.995f, ONE_M = 0.005f;
        float nmin = act_range[2 * t]     * SMOOTH + cmin * ONE_M;
        float nmax = act_range[2 * t + 1] * SMOOTH + cmax * ONE_M;
        float s = (nmax - nmin) * (1.0f / 255.0f);
        cs_s[t] = s;
        cs_z[t] = -rintf(nmin / s);
    }
    __syncthreads();
    if (t < B_) {
        int k = cluster[t];
        g_ss[t]  = cs_s[k];
        g_zz[t]  = cs_z[k];
        g_inv[t] = 1.0f / cs_s[k];
    }
}

// ---------------- kernel 4: fake-quant, 2 planes/block, 8 batched loads -----
__device__ __forceinline__ float fq1(float xv, float sc, float inv,
                                     float ssv, float zzv) {
    float o = sc * xv;
    float q = fminf(fmaxf(rintf(fmaf(o, inv, zzv)), 0.0f), 255.0f);
    return (q - zzv) * ssv;
}

__global__ __launch_bounds__(256) void k4_quant(const float* __restrict__ x,
                                                float* __restrict__ out) {
    const int p0 = blockIdx.x * 2;                 // p0 and p0+1: same sample b
    const int b  = p0 >> 8;
    const float sc0 = g_scale[p0];
    const float sc1 = g_scale[p0 + 1];
    const float ssv = g_ss[b];
    const float zzv = g_zz[b];
    const float inv = g_inv[b];
    const int t = threadIdx.x;

    const float4* xp0 = reinterpret_cast<const float4*>(x + (size_t)p0 * HW_);
    const float4* xp1 = xp0 + (HW_ / 4);
    float4* op0 = reinterpret_cast<float4*>(out + (size_t)p0 * HW_);
    float4* op1 = op0 + (HW_ / 4);

    // batch all 8 loads before any compute/store -> max read MLP
    float4 va[4], vb[4];
#pragma unroll
    for (int i = 0; i < 4; ++i) va[i] = xp0[t + 256 * i];
#pragma unroll
    for (int i = 0; i < 4; ++i) vb[i] = xp1[t + 256 * i];

#pragma unroll
    for (int i = 0; i < 4; ++i) {
        float4 r;
        r.x = fq1(va[i].x, sc0, inv, ssv, zzv);
        r.y = fq1(va[i].y, sc0, inv, ssv, zzv);
        r.z = fq1(va[i].z, sc0, inv, ssv, zzv);
        r.w = fq1(va[i].w, sc0, inv, ssv, zzv);
        op0[t + 256 * i] = r;
    }
#pragma unroll
    for (int i = 0; i < 4; ++i) {
        float4 r;
        r.x = fq1(vb[i].x, sc1, inv, ssv, zzv);
        r.y = fq1(vb[i].y, sc1, inv, ssv, zzv);
        r.z = fq1(vb[i].z, sc1, inv, ssv, zzv);
        r.w = fq1(vb[i].w, sc1, inv, ssv, zzv);
        op1[t + 256 * i] = r;
    }
}

// ---------------- launch ----------------------------------------------------
extern "C" void kernel_launch(void* const* d_in, const int* in_sizes, int n_in,
                              void* d_out, int out_size) {
    const float* x          = (const float*)d_in[0];
    const float* w1         = (const float*)d_in[1];
    const float* b1         = (const float*)d_in[2];
    const float* w2         = (const float*)d_in[3];
    const float* b2         = (const float*)d_in[4];
    const float* act_range  = (const float*)d_in[5];
    const int*   cluster    = (const int*)d_in[6];
    float* out = (float*)d_out;

    k1_reduce<<<NPLANE / 8, 256>>>(x);
    k2_se<<<B_, 256>>>(w1, b1, w2, b2, act_range, cluster);
    k4_quant<<<NPLANE / 2, 256>>>(x, out);
}